// round 1
// baseline (speedup 1.0000x reference)
#include <cuda_runtime.h>
#include <math.h>

// ---------------- problem constants ----------------
constexpr int Tt   = 12;
constexpr int Nn   = 30000;
constexpr int Ee   = 480000;
constexpr int FIN  = 128;
constexpr int H1C  = 256;
constexpr int H2C  = 128;
constexpr int RAWC = 20;
constexpr int HID  = 256;
constexpr int OUTC = 64;
constexpr int DSEQ = H2C + RAWC;   // 148
constexpr int G4   = 4 * HID;      // 1024
constexpr size_t NT = (size_t)Nn * Tt;  // 360000

// ---------------- scratch (device globals; no allocation allowed) ----------------
__device__ float g_bufA[NT * 256];        // support1 -> support2 -> h_seq1
__device__ float g_bufX[NT * 256];        // x (gcn layer1 out) -> h_seq0
__device__ float g_seq [NT * DSEQ];       // [n,t,148]
__device__ float g_xg  [NT * (size_t)G4]; // [n,t,1024] input gates (layer0 then layer1)
__device__ float g_R   [(size_t)Nn * G4]; // per-step recurrent gemm out
__device__ float g_h   [(size_t)Nn * HID];
__device__ float g_c   [(size_t)Nn * HID];
__device__ float g_pool[(size_t)Nn * HID];
__device__ float g_z   [(size_t)Nn * 128];

// ---------------- generic tiled fp32 GEMM ----------------
// C[M,Nc] = op(A)[M,K] * B(+opt trans) + bias, optional relu on A-load and on C.
// btrans=0: B stored [K,Nc] row-major.  btrans=1: B stored [Nc,K] row-major (use B^T).
template<int BM, int BN, int BK, int TM, int TN>
__global__ void sgemm_kernel(const float* __restrict__ A, const float* __restrict__ B,
                             float* __restrict__ C, const float* __restrict__ bias,
                             int M, int K, int Nc,
                             int btrans, int relu_a, int relu_c)
{
    __shared__ float As[BK][BM];
    __shared__ float Bs[BK][BN];
    const int tid = threadIdx.x;                 // 256 threads
    const int brow = blockIdx.y * BM;
    const int bcol = blockIdx.x * BN;
    const int trow = (tid / (BN / TN)) * TM;
    const int tcol = (tid % (BN / TN)) * TN;

    float acc[TM][TN];
#pragma unroll
    for (int i = 0; i < TM; i++)
#pragma unroll
        for (int j = 0; j < TN; j++) acc[i][j] = 0.f;

    for (int k0 = 0; k0 < K; k0 += BK) {
        // load A tile (BM x BK)
#pragma unroll
        for (int i = 0; i < (BM * BK) / 256; i++) {
            int l = tid + i * 256;
            int m = l / BK, k = l % BK;
            int gr = brow + m, gk = k0 + k;
            float v = 0.f;
            if (gr < M && gk < K) v = A[(size_t)gr * K + gk];
            if (relu_a) v = fmaxf(v, 0.f);
            As[k][m] = v;
        }
        // load B tile (BK x BN)
        if (!btrans) {
#pragma unroll
            for (int i = 0; i < (BK * BN) / 256; i++) {
                int l = tid + i * 256;
                int k = l / BN, n = l % BN;
                int gk = k0 + k, gn = bcol + n;
                float v = 0.f;
                if (gk < K && gn < Nc) v = B[(size_t)gk * Nc + gn];
                Bs[k][n] = v;
            }
        } else {
#pragma unroll
            for (int i = 0; i < (BK * BN) / 256; i++) {
                int l = tid + i * 256;
                int n = l / BK, k = l % BK;
                int gk = k0 + k, gn = bcol + n;
                float v = 0.f;
                if (gk < K && gn < Nc) v = B[(size_t)gn * K + gk];
                Bs[k][n] = v;
            }
        }
        __syncthreads();
#pragma unroll
        for (int k = 0; k < BK; k++) {
            float ar[TM], br[TN];
#pragma unroll
            for (int i = 0; i < TM; i++) ar[i] = As[k][trow + i];
#pragma unroll
            for (int j = 0; j < TN; j++) br[j] = Bs[k][tcol + j];
#pragma unroll
            for (int i = 0; i < TM; i++)
#pragma unroll
                for (int j = 0; j < TN; j++) acc[i][j] = fmaf(ar[i], br[j], acc[i][j]);
        }
        __syncthreads();
    }
#pragma unroll
    for (int i = 0; i < TM; i++) {
        int gr = brow + trow + i;
        if (gr >= M) continue;
#pragma unroll
        for (int j = 0; j < TN; j++) {
            int gn = bcol + tcol + j;
            if (gn >= Nc) continue;
            float v = acc[i][j];
            if (bias) v += bias[gn];
            if (relu_c) v = fmaxf(v, 0.f);
            C[(size_t)gr * Nc + gn] = v;
        }
    }
}

static inline void sgemm(const float* A, const float* B, float* C, const float* bias,
                         int M, int K, int Nc, int btrans, int relu_a, int relu_c)
{
    dim3 grid((Nc + 63) / 64, (M + 63) / 64);
    sgemm_kernel<64, 64, 16, 4, 4><<<grid, 256>>>(A, B, C, bias, M, K, Nc, btrans, relu_a, relu_c);
}

// ---------------- SpMM: warp-per-edge scatter with atomics ----------------
// dst pre-initialized with bias; dst layout: 0 -> row (t*N + r), 1 -> row (r*T + t)
__global__ void spmm_scatter(const float* __restrict__ src,
                             const int* __restrict__ erow, const int* __restrict__ ecol,
                             const float* __restrict__ ew,
                             float* __restrict__ dst,
                             int ncols, int src_ld, int dst_ld, int dst_layout)
{
    long long warp = ((long long)blockIdx.x * blockDim.x + threadIdx.x) >> 5;
    int lane = threadIdx.x & 31;
    if (warp >= (long long)Tt * Ee) return;
    int t = (int)(warp / Ee);
    int e = (int)(warp % Ee);
    size_t eoff = (size_t)t * Ee + e;
    int r = erow[eoff];
    int c = ecol[eoff];
    float w = ew[eoff];
    const float* s = src + ((size_t)t * Nn + c) * src_ld;
    size_t doff = (dst_layout == 0) ? ((size_t)t * Nn + r) * (size_t)dst_ld
                                    : ((size_t)r * Tt + t) * (size_t)dst_ld;
    float* d = dst + doff;
    for (int j = lane; j < ncols; j += 32) atomicAdd(&d[j], w * s[j]);
}

// ---------------- init kernels ----------------
__global__ void init_bias_bcast(float* __restrict__ dst, const float* __restrict__ bias,
                                int C, size_t total)
{
    size_t stride = (size_t)gridDim.x * blockDim.x;
    for (size_t i = (size_t)blockIdx.x * blockDim.x + threadIdx.x; i < total; i += stride)
        dst[i] = bias[i % C];
}

// seq[n,t,c]: c<128 -> b2[c], else raw[t,n,c-128]
__global__ void init_seq(float* __restrict__ seq, const float* __restrict__ b2,
                         const float* __restrict__ raw, size_t total)
{
    size_t stride = (size_t)gridDim.x * blockDim.x;
    for (size_t i = (size_t)blockIdx.x * blockDim.x + threadIdx.x; i < total; i += stride) {
        int c = (int)(i % DSEQ);
        size_t nt = i / DSEQ;
        int t = (int)(nt % Tt);
        size_t n = nt / Tt;
        seq[i] = (c < H2C) ? b2[c]
                           : raw[(size_t)t * Nn * RAWC + n * RAWC + (c - H2C)];
    }
}

// ---------------- LSTM pointwise update ----------------
__device__ __forceinline__ float sigmoidf_(float x) { return 1.f / (1.f + expf(-x)); }

__global__ void lstm_update(const float* __restrict__ xg,   // [n*T+t, 1024]
                            const float* __restrict__ R,    // [n, 1024] (includes bhh)
                            float* __restrict__ cst, float* __restrict__ hst,
                            float* __restrict__ hseq, int t)
{
    size_t idx = (size_t)blockIdx.x * blockDim.x + threadIdx.x;
    if (idx >= (size_t)Nn * HID) return;
    size_t n = idx / HID;
    int j = (int)(idx % HID);
    const float* xr = xg + ((size_t)n * Tt + t) * G4;
    const float* rr = R + n * (size_t)G4;
    float gi = xr[j]           + rr[j];
    float gf = xr[HID + j]     + rr[HID + j];
    float gg = xr[2 * HID + j] + rr[2 * HID + j];
    float go = xr[3 * HID + j] + rr[3 * HID + j];
    float cn = sigmoidf_(gf) * cst[idx] + sigmoidf_(gi) * tanhf(gg);
    float hn = sigmoidf_(go) * tanhf(cn);
    cst[idx] = cn;
    hst[idx] = hn;
    hseq[((size_t)n * Tt + t) * HID + j] = hn;
}

// ---------------- attention pooling ----------------
__global__ void attention_pool(const float* __restrict__ hseq,  // [n*T+t, 256]
                               const float* __restrict__ att_w, // [256]
                               const float* __restrict__ att_b, // [1]
                               float* __restrict__ pooled)      // [n, 256]
{
    __shared__ float hs[Tt * HID];
    __shared__ float aw[HID];
    __shared__ float red[HID];
    __shared__ float sc[Tt];
    int n = blockIdx.x;
    int tid = threadIdx.x;  // 256
    const float* base = hseq + (size_t)n * Tt * HID;
#pragma unroll
    for (int i = 0; i < Tt; i++) hs[i * HID + tid] = base[i * HID + tid];
    aw[tid] = att_w[tid];
    __syncthreads();
    float ab = att_b[0];
    for (int t = 0; t < Tt; t++) {
        red[tid] = hs[t * HID + tid] * aw[tid];
        __syncthreads();
        for (int s = HID / 2; s > 0; s >>= 1) {
            if (tid < s) red[tid] += red[tid + s];
            __syncthreads();
        }
        if (tid == 0) sc[t] = red[0] + ab;
        __syncthreads();
    }
    // softmax over T (redundant per thread)
    float mx = -1e30f;
#pragma unroll
    for (int t = 0; t < Tt; t++) mx = fmaxf(mx, sc[t]);
    float a[Tt], sum = 0.f;
#pragma unroll
    for (int t = 0; t < Tt; t++) { a[t] = expf(sc[t] - mx); sum += a[t]; }
    float p = 0.f;
#pragma unroll
    for (int t = 0; t < Tt; t++) p += a[t] * hs[t * HID + tid];
    pooled[(size_t)n * HID + tid] = p / sum;
}

// ---------------- launch ----------------
extern "C" void kernel_launch(void* const* d_in, const int* in_sizes, int n_in,
                              void* d_out, int out_size)
{
    const float* nodes = (const float*)d_in[0];
    const int*   erow  = (const int*)  d_in[1];
    const int*   ecol  = (const int*)  d_in[2];
    const float* ew    = (const float*)d_in[3];
    const float* raw   = (const float*)d_in[4];
    const float* W1    = (const float*)d_in[5];
    const float* b1    = (const float*)d_in[6];
    const float* W2    = (const float*)d_in[7];
    const float* b2    = (const float*)d_in[8];
    const float* Wih0  = (const float*)d_in[9];
    const float* Whh0  = (const float*)d_in[10];
    const float* bih0  = (const float*)d_in[11];
    const float* bhh0  = (const float*)d_in[12];
    const float* Wih1  = (const float*)d_in[13];
    const float* Whh1  = (const float*)d_in[14];
    const float* bih1  = (const float*)d_in[15];
    const float* bhh1  = (const float*)d_in[16];
    const float* att_w = (const float*)d_in[17];
    const float* att_b = (const float*)d_in[18];
    const float* fcn_w = (const float*)d_in[19];
    const float* fcn_b = (const float*)d_in[20];
    const float* out_w = (const float*)d_in[21];
    const float* out_b = (const float*)d_in[22];
    float* out = (float*)d_out;

    float *bufA, *bufX, *seq, *xg, *R, *hst, *cst, *pooled, *z;
    cudaGetSymbolAddress((void**)&bufA,   g_bufA);
    cudaGetSymbolAddress((void**)&bufX,   g_bufX);
    cudaGetSymbolAddress((void**)&seq,    g_seq);
    cudaGetSymbolAddress((void**)&xg,     g_xg);
    cudaGetSymbolAddress((void**)&R,      g_R);
    cudaGetSymbolAddress((void**)&hst,    g_h);
    cudaGetSymbolAddress((void**)&cst,    g_c);
    cudaGetSymbolAddress((void**)&pooled, g_pool);
    cudaGetSymbolAddress((void**)&z,      g_z);

    const int M = (int)NT;  // 360000

    // 1) support1 = nodes @ W1   [NT,128]x[128,256]
    sgemm(nodes, W1, bufA, nullptr, M, FIN, H1C, 0, 0, 0);

    // 2) x := b1 (broadcast), scatter-add spmm(support1), relu folded into next gemm
    {
        size_t tot = NT * (size_t)H1C;
        init_bias_bcast<<<8192, 256>>>(bufX, b1, H1C, tot);
        long long warps = (long long)Tt * Ee;
        long long blocks = (warps * 32 + 255) / 256;
        spmm_scatter<<<(unsigned)blocks, 256>>>(bufA, erow, ecol, ew, bufX, H1C, H1C, H1C, 0);
    }

    // 3) support2 = relu(x) @ W2   [NT,256]x[256,128] -> bufA (ld=128)
    sgemm(bufX, W2, bufA, nullptr, M, H1C, H2C, 0, 1, 0);

    // 4) seq init (b2 + raw), spmm2 scatter into seq (embed part)
    {
        size_t tot = NT * (size_t)DSEQ;
        init_seq<<<8192, 256>>>(seq, b2, raw, tot);
        long long warps = (long long)Tt * Ee;
        long long blocks = (warps * 32 + 255) / 256;
        spmm_scatter<<<(unsigned)blocks, 256>>>(bufA, erow, ecol, ew, seq, H2C, H2C, DSEQ, 1);
    }

    // 5) xg0 = seq @ Wih0^T + bih0   [NT,148]x[148,1024]
    sgemm(seq, Wih0, xg, bih0, M, DSEQ, G4, 1, 0, 0);

    // 6) LSTM layer 0 -> h_seq0 = bufX (reused)
    cudaMemsetAsync(hst, 0, (size_t)Nn * HID * sizeof(float));
    cudaMemsetAsync(cst, 0, (size_t)Nn * HID * sizeof(float));
    for (int t = 0; t < Tt; t++) {
        sgemm(hst, Whh0, R, bhh0, Nn, HID, G4, 1, 0, 0);
        int blocks = (int)(((size_t)Nn * HID + 255) / 256);
        lstm_update<<<blocks, 256>>>(xg, R, cst, hst, bufX, t);
    }

    // 7) xg1 = h_seq0 @ Wih1^T + bih1   [NT,256]x[256,1024]
    sgemm(bufX, Wih1, xg, bih1, M, HID, G4, 1, 0, 0);

    // 8) LSTM layer 1 -> h_seq1 = bufA (reused)
    cudaMemsetAsync(hst, 0, (size_t)Nn * HID * sizeof(float));
    cudaMemsetAsync(cst, 0, (size_t)Nn * HID * sizeof(float));
    for (int t = 0; t < Tt; t++) {
        sgemm(hst, Whh1, R, bhh1, Nn, HID, G4, 1, 0, 0);
        int blocks = (int)(((size_t)Nn * HID + 255) / 256);
        lstm_update<<<blocks, 256>>>(xg, R, cst, hst, bufA, t);
    }

    // 9) attention pooling over time
    attention_pool<<<Nn, HID>>>(bufA, att_w, att_b, pooled);

    // 10) z = relu(pooled @ fcn_w + fcn_b)   [30000,256]x[256,128]
    sgemm(pooled, fcn_w, z, fcn_b, Nn, HID, 128, 0, 0, 1);

    // 11) out = z @ out_w + out_b   [30000,128]x[128,64]
    sgemm(z, out_w, out, out_b, Nn, 128, OUTC, 0, 0, 0);
}

// round 2
// speedup vs baseline: 2.0077x; 2.0077x over previous
#include <cuda_runtime.h>
#include <math.h>

// ---------------- problem constants ----------------
constexpr int Tt   = 12;
constexpr int Nn   = 30000;
constexpr int Ee   = 480000;
constexpr int FIN  = 128;
constexpr int H1C  = 256;
constexpr int H2C  = 128;
constexpr int RAWC = 20;
constexpr int HID  = 256;
constexpr int OUTC = 64;
constexpr int DSEQ = H2C + RAWC;   // 148
constexpr int G4   = 4 * HID;      // 1024
constexpr size_t NT = (size_t)Nn * Tt;  // 360000

// ---------------- scratch (device globals; no allocation allowed) ----------------
__device__ float g_bufA[NT * 256];        // support1 -> support2 -> h_seq1
__device__ float g_bufX[NT * 256];        // x (gcn layer1 out) -> h_seq0
__device__ float g_seq [NT * DSEQ];       // [n,t,148]
__device__ float g_xg  [NT * (size_t)G4]; // [n,t,1024] input gates (layer0 then layer1)
__device__ float g_R   [(size_t)Nn * G4]; // per-step recurrent gemm out
__device__ float g_h   [(size_t)Nn * HID];
__device__ float g_c   [(size_t)Nn * HID];
__device__ float g_pool[(size_t)Nn * HID];
__device__ float g_z   [(size_t)Nn * 128];

// =====================================================================
// Fast 128x128x8 fp32 GEMM, 8x8 per thread, 256 threads, float4 paths.
// C[M,Nc] = op(A)[M,K] * B(+opt trans) + bias, optional relu on A and C.
// Requires K % 4 == 0 (true for all call sites: 128/148/256).
// btrans=0: B stored [K,Nc]; btrans=1: B stored [Nc,K] (use B^T).
// =====================================================================
__global__ void __launch_bounds__(256) sgemm128_kernel(
    const float* __restrict__ A, const float* __restrict__ B,
    float* __restrict__ C, const float* __restrict__ bias,
    int M, int K, int Nc, int btrans, int relu_a, int relu_c)
{
    __shared__ float As[8][128];
    __shared__ float Bs[8][128];
    const int tid  = threadIdx.x;
    const int brow = blockIdx.y * 128;
    const int bcol = blockIdx.x * 128;

    // A tile load mapping: 128 rows x 8 k; one float4 per thread
    const int arow = tid >> 1;            // 0..127
    const int ak   = (tid & 1) << 2;      // 0 or 4
    // B tile load mapping (btrans=0): 8 k x 128 n
    const int b0k  = tid >> 5;            // 0..7
    const int b0n  = (tid & 31) << 2;     // 0..124
    // B tile load mapping (btrans=1): 128 n x 8 k
    const int b1n  = tid >> 1;
    const int b1k  = (tid & 1) << 2;

    const int trow = (tid >> 4) << 3;     // 0..120
    const int tcol = (tid & 15) << 3;     // 0..120

    float acc[8][8];
#pragma unroll
    for (int i = 0; i < 8; i++)
#pragma unroll
        for (int j = 0; j < 8; j++) acc[i][j] = 0.f;

    auto loadA = [&](int k0) -> float4 {
        int gr = brow + arow, gk = k0 + ak;
        float4 v = make_float4(0.f, 0.f, 0.f, 0.f);
        if (gr < M && gk < K) {
            v = *reinterpret_cast<const float4*>(&A[(size_t)gr * K + gk]);
            if (relu_a) {
                v.x = fmaxf(v.x, 0.f); v.y = fmaxf(v.y, 0.f);
                v.z = fmaxf(v.z, 0.f); v.w = fmaxf(v.w, 0.f);
            }
        }
        return v;
    };
    auto loadB = [&](int k0) -> float4 {
        float4 v = make_float4(0.f, 0.f, 0.f, 0.f);
        if (!btrans) {
            int gk = k0 + b0k, gn = bcol + b0n;
            if (gk < K && gn < Nc)
                v = *reinterpret_cast<const float4*>(&B[(size_t)gk * Nc + gn]);
        } else {
            int gn = bcol + b1n, gk = k0 + b1k;
            if (gn < Nc && gk < K)
                v = *reinterpret_cast<const float4*>(&B[(size_t)gn * K + gk]);
        }
        return v;
    };

    float4 aR = loadA(0);
    float4 bR = loadB(0);

    for (int k0 = 0; k0 < K; k0 += 8) {
        // commit staged tiles to smem
        As[ak + 0][arow] = aR.x; As[ak + 1][arow] = aR.y;
        As[ak + 2][arow] = aR.z; As[ak + 3][arow] = aR.w;
        if (!btrans) {
            *reinterpret_cast<float4*>(&Bs[b0k][b0n]) = bR;
        } else {
            Bs[b1k + 0][b1n] = bR.x; Bs[b1k + 1][b1n] = bR.y;
            Bs[b1k + 2][b1n] = bR.z; Bs[b1k + 3][b1n] = bR.w;
        }
        __syncthreads();

        // prefetch next tile while computing this one
        if (k0 + 8 < K) { aR = loadA(k0 + 8); bR = loadB(k0 + 8); }

#pragma unroll
        for (int k = 0; k < 8; k++) {
            float4 a0 = *reinterpret_cast<const float4*>(&As[k][trow]);
            float4 a1 = *reinterpret_cast<const float4*>(&As[k][trow + 4]);
            float4 c0 = *reinterpret_cast<const float4*>(&Bs[k][tcol]);
            float4 c1 = *reinterpret_cast<const float4*>(&Bs[k][tcol + 4]);
            float ar[8] = {a0.x, a0.y, a0.z, a0.w, a1.x, a1.y, a1.z, a1.w};
            float br[8] = {c0.x, c0.y, c0.z, c0.w, c1.x, c1.y, c1.z, c1.w};
#pragma unroll
            for (int i = 0; i < 8; i++)
#pragma unroll
                for (int j = 0; j < 8; j++)
                    acc[i][j] = fmaf(ar[i], br[j], acc[i][j]);
        }
        __syncthreads();
    }

    // epilogue
    float bv[8];
#pragma unroll
    for (int j = 0; j < 8; j++) {
        int gn = bcol + tcol + j;
        bv[j] = (bias && gn < Nc) ? bias[gn] : 0.f;
    }
    bool colok = (bcol + tcol + 8 <= Nc);
#pragma unroll
    for (int i = 0; i < 8; i++) {
        int gr = brow + trow + i;
        if (gr >= M) continue;
        if (colok) {
            float4 v0, v1;
            v0.x = acc[i][0] + bv[0]; v0.y = acc[i][1] + bv[1];
            v0.z = acc[i][2] + bv[2]; v0.w = acc[i][3] + bv[3];
            v1.x = acc[i][4] + bv[4]; v1.y = acc[i][5] + bv[5];
            v1.z = acc[i][6] + bv[6]; v1.w = acc[i][7] + bv[7];
            if (relu_c) {
                v0.x = fmaxf(v0.x, 0.f); v0.y = fmaxf(v0.y, 0.f);
                v0.z = fmaxf(v0.z, 0.f); v0.w = fmaxf(v0.w, 0.f);
                v1.x = fmaxf(v1.x, 0.f); v1.y = fmaxf(v1.y, 0.f);
                v1.z = fmaxf(v1.z, 0.f); v1.w = fmaxf(v1.w, 0.f);
            }
            float* cp = &C[(size_t)gr * Nc + bcol + tcol];
            *reinterpret_cast<float4*>(cp)     = v0;
            *reinterpret_cast<float4*>(cp + 4) = v1;
        } else {
#pragma unroll
            for (int j = 0; j < 8; j++) {
                int gn = bcol + tcol + j;
                if (gn >= Nc) continue;
                float v = acc[i][j] + bv[j];
                if (relu_c) v = fmaxf(v, 0.f);
                C[(size_t)gr * Nc + gn] = v;
            }
        }
    }
}

// ---------------- fallback tiled fp32 GEMM (small N) ----------------
template<int BM, int BN, int BK, int TM, int TN>
__global__ void sgemm_kernel(const float* __restrict__ A, const float* __restrict__ B,
                             float* __restrict__ C, const float* __restrict__ bias,
                             int M, int K, int Nc,
                             int btrans, int relu_a, int relu_c)
{
    __shared__ float As[BK][BM];
    __shared__ float Bs[BK][BN];
    const int tid = threadIdx.x;                 // 256 threads
    const int brow = blockIdx.y * BM;
    const int bcol = blockIdx.x * BN;
    const int trow = (tid / (BN / TN)) * TM;
    const int tcol = (tid % (BN / TN)) * TN;

    float acc[TM][TN];
#pragma unroll
    for (int i = 0; i < TM; i++)
#pragma unroll
        for (int j = 0; j < TN; j++) acc[i][j] = 0.f;

    for (int k0 = 0; k0 < K; k0 += BK) {
#pragma unroll
        for (int i = 0; i < (BM * BK) / 256; i++) {
            int l = tid + i * 256;
            int m = l / BK, k = l % BK;
            int gr = brow + m, gk = k0 + k;
            float v = 0.f;
            if (gr < M && gk < K) v = A[(size_t)gr * K + gk];
            if (relu_a) v = fmaxf(v, 0.f);
            As[k][m] = v;
        }
        if (!btrans) {
#pragma unroll
            for (int i = 0; i < (BK * BN) / 256; i++) {
                int l = tid + i * 256;
                int k = l / BN, n = l % BN;
                int gk = k0 + k, gn = bcol + n;
                float v = 0.f;
                if (gk < K && gn < Nc) v = B[(size_t)gk * Nc + gn];
                Bs[k][n] = v;
            }
        } else {
#pragma unroll
            for (int i = 0; i < (BK * BN) / 256; i++) {
                int l = tid + i * 256;
                int n = l / BK, k = l % BK;
                int gk = k0 + k, gn = bcol + n;
                float v = 0.f;
                if (gk < K && gn < Nc) v = B[(size_t)gn * K + gk];
                Bs[k][n] = v;
            }
        }
        __syncthreads();
#pragma unroll
        for (int k = 0; k < BK; k++) {
            float ar[TM], br[TN];
#pragma unroll
            for (int i = 0; i < TM; i++) ar[i] = As[k][trow + i];
#pragma unroll
            for (int j = 0; j < TN; j++) br[j] = Bs[k][tcol + j];
#pragma unroll
            for (int i = 0; i < TM; i++)
#pragma unroll
                for (int j = 0; j < TN; j++) acc[i][j] = fmaf(ar[i], br[j], acc[i][j]);
        }
        __syncthreads();
    }
#pragma unroll
    for (int i = 0; i < TM; i++) {
        int gr = brow + trow + i;
        if (gr >= M) continue;
#pragma unroll
        for (int j = 0; j < TN; j++) {
            int gn = bcol + tcol + j;
            if (gn >= Nc) continue;
            float v = acc[i][j];
            if (bias) v += bias[gn];
            if (relu_c) v = fmaxf(v, 0.f);
            C[(size_t)gr * Nc + gn] = v;
        }
    }
}

static inline void sgemm(const float* A, const float* B, float* C, const float* bias,
                         int M, int K, int Nc, int btrans, int relu_a, int relu_c)
{
    if ((Nc % 128) == 0 && (K % 4) == 0) {
        dim3 grid(Nc / 128, (M + 127) / 128);
        sgemm128_kernel<<<grid, 256>>>(A, B, C, bias, M, K, Nc, btrans, relu_a, relu_c);
    } else {
        dim3 grid((Nc + 63) / 64, (M + 63) / 64);
        sgemm_kernel<64, 64, 16, 4, 4><<<grid, 256>>>(A, B, C, bias, M, K, Nc, btrans, relu_a, relu_c);
    }
}

// ---------------- SpMM: warp-per-edge scatter with atomics ----------------
__global__ void spmm_scatter(const float* __restrict__ src,
                             const int* __restrict__ erow, const int* __restrict__ ecol,
                             const float* __restrict__ ew,
                             float* __restrict__ dst,
                             int ncols, int src_ld, int dst_ld, int dst_layout)
{
    long long warp = ((long long)blockIdx.x * blockDim.x + threadIdx.x) >> 5;
    int lane = threadIdx.x & 31;
    if (warp >= (long long)Tt * Ee) return;
    int t = (int)(warp / Ee);
    int e = (int)(warp % Ee);
    size_t eoff = (size_t)t * Ee + e;
    int r = erow[eoff];
    int c = ecol[eoff];
    float w = ew[eoff];
    const float* s = src + ((size_t)t * Nn + c) * src_ld;
    size_t doff = (dst_layout == 0) ? ((size_t)t * Nn + r) * (size_t)dst_ld
                                    : ((size_t)r * Tt + t) * (size_t)dst_ld;
    float* d = dst + doff;
    for (int j = lane; j < ncols; j += 32) atomicAdd(&d[j], w * s[j]);
}

// ---------------- init kernels ----------------
__global__ void init_bias_bcast(float* __restrict__ dst, const float* __restrict__ bias,
                                int C, size_t total)
{
    size_t stride = (size_t)gridDim.x * blockDim.x;
    for (size_t i = (size_t)blockIdx.x * blockDim.x + threadIdx.x; i < total; i += stride)
        dst[i] = bias[i % C];
}

__global__ void init_seq(float* __restrict__ seq, const float* __restrict__ b2,
                         const float* __restrict__ raw, size_t total)
{
    size_t stride = (size_t)gridDim.x * blockDim.x;
    for (size_t i = (size_t)blockIdx.x * blockDim.x + threadIdx.x; i < total; i += stride) {
        int c = (int)(i % DSEQ);
        size_t nt = i / DSEQ;
        int t = (int)(nt % Tt);
        size_t n = nt / Tt;
        seq[i] = (c < H2C) ? b2[c]
                           : raw[(size_t)t * Nn * RAWC + n * RAWC + (c - H2C)];
    }
}

// ---------------- LSTM pointwise update ----------------
__device__ __forceinline__ float sigmoidf_(float x) { return 1.f / (1.f + expf(-x)); }

// R==nullptr means h_{t-1}==0: recurrent contribution is just bhh.
__global__ void lstm_update(const float* __restrict__ xg,   // [n*T+t, 1024]
                            const float* __restrict__ R,    // [n, 1024] (includes bhh) or null
                            const float* __restrict__ bhh,  // [1024]
                            float* __restrict__ cst, float* __restrict__ hst,
                            float* __restrict__ hseq, int t)
{
    size_t idx = (size_t)blockIdx.x * blockDim.x + threadIdx.x;
    if (idx >= (size_t)Nn * HID) return;
    size_t n = idx / HID;
    int j = (int)(idx % HID);
    const float* xr = xg + ((size_t)n * Tt + t) * G4;
    float ri, rf, rg, ro;
    if (R) {
        const float* rr = R + n * (size_t)G4;
        ri = rr[j]; rf = rr[HID + j]; rg = rr[2 * HID + j]; ro = rr[3 * HID + j];
    } else {
        ri = bhh[j]; rf = bhh[HID + j]; rg = bhh[2 * HID + j]; ro = bhh[3 * HID + j];
    }
    float gi = xr[j]           + ri;
    float gf = xr[HID + j]     + rf;
    float gg = xr[2 * HID + j] + rg;
    float go = xr[3 * HID + j] + ro;
    float cprev = (R) ? cst[idx] : 0.f;
    float cn = sigmoidf_(gf) * cprev + sigmoidf_(gi) * tanhf(gg);
    float hn = sigmoidf_(go) * tanhf(cn);
    cst[idx] = cn;
    hst[idx] = hn;
    hseq[((size_t)n * Tt + t) * HID + j] = hn;
}

// ---------------- attention pooling ----------------
__global__ void attention_pool(const float* __restrict__ hseq,  // [n*T+t, 256]
                               const float* __restrict__ att_w, // [256]
                               const float* __restrict__ att_b, // [1]
                               float* __restrict__ pooled)      // [n, 256]
{
    __shared__ float hs[Tt * HID];
    __shared__ float aw[HID];
    __shared__ float red[HID];
    __shared__ float sc[Tt];
    int n = blockIdx.x;
    int tid = threadIdx.x;  // 256
    const float* base = hseq + (size_t)n * Tt * HID;
#pragma unroll
    for (int i = 0; i < Tt; i++) hs[i * HID + tid] = base[i * HID + tid];
    aw[tid] = att_w[tid];
    __syncthreads();
    float ab = att_b[0];
    for (int t = 0; t < Tt; t++) {
        red[tid] = hs[t * HID + tid] * aw[tid];
        __syncthreads();
        for (int s = HID / 2; s > 0; s >>= 1) {
            if (tid < s) red[tid] += red[tid + s];
            __syncthreads();
        }
        if (tid == 0) sc[t] = red[0] + ab;
        __syncthreads();
    }
    float mx = -1e30f;
#pragma unroll
    for (int t = 0; t < Tt; t++) mx = fmaxf(mx, sc[t]);
    float a[Tt], sum = 0.f;
#pragma unroll
    for (int t = 0; t < Tt; t++) { a[t] = expf(sc[t] - mx); sum += a[t]; }
    float p = 0.f;
#pragma unroll
    for (int t = 0; t < Tt; t++) p += a[t] * hs[t * HID + tid];
    pooled[(size_t)n * HID + tid] = p / sum;
}

// ---------------- launch ----------------
extern "C" void kernel_launch(void* const* d_in, const int* in_sizes, int n_in,
                              void* d_out, int out_size)
{
    const float* nodes = (const float*)d_in[0];
    const int*   erow  = (const int*)  d_in[1];
    const int*   ecol  = (const int*)  d_in[2];
    const float* ew    = (const float*)d_in[3];
    const float* raw   = (const float*)d_in[4];
    const float* W1    = (const float*)d_in[5];
    const float* b1    = (const float*)d_in[6];
    const float* W2    = (const float*)d_in[7];
    const float* b2    = (const float*)d_in[8];
    const float* Wih0  = (const float*)d_in[9];
    const float* Whh0  = (const float*)d_in[10];
    const float* bih0  = (const float*)d_in[11];
    const float* bhh0  = (const float*)d_in[12];
    const float* Wih1  = (const float*)d_in[13];
    const float* Whh1  = (const float*)d_in[14];
    const float* bih1  = (const float*)d_in[15];
    const float* bhh1  = (const float*)d_in[16];
    const float* att_w = (const float*)d_in[17];
    const float* att_b = (const float*)d_in[18];
    const float* fcn_w = (const float*)d_in[19];
    const float* fcn_b = (const float*)d_in[20];
    const float* out_w = (const float*)d_in[21];
    const float* out_b = (const float*)d_in[22];
    float* out = (float*)d_out;

    float *bufA, *bufX, *seq, *xg, *R, *hst, *cst, *pooled, *z;
    cudaGetSymbolAddress((void**)&bufA,   g_bufA);
    cudaGetSymbolAddress((void**)&bufX,   g_bufX);
    cudaGetSymbolAddress((void**)&seq,    g_seq);
    cudaGetSymbolAddress((void**)&xg,     g_xg);
    cudaGetSymbolAddress((void**)&R,      g_R);
    cudaGetSymbolAddress((void**)&hst,    g_h);
    cudaGetSymbolAddress((void**)&cst,    g_c);
    cudaGetSymbolAddress((void**)&pooled, g_pool);
    cudaGetSymbolAddress((void**)&z,      g_z);

    const int M = (int)NT;  // 360000
    const int upd_blocks = (int)(((size_t)Nn * HID + 255) / 256);

    // 1) support1 = nodes @ W1   [NT,128]x[128,256]
    sgemm(nodes, W1, bufA, nullptr, M, FIN, H1C, 0, 0, 0);

    // 2) x := b1 (broadcast), scatter-add spmm(support1); relu folded into next gemm
    {
        size_t tot = NT * (size_t)H1C;
        init_bias_bcast<<<8192, 256>>>(bufX, b1, H1C, tot);
        long long warps = (long long)Tt * Ee;
        long long blocks = (warps * 32 + 255) / 256;
        spmm_scatter<<<(unsigned)blocks, 256>>>(bufA, erow, ecol, ew, bufX, H1C, H1C, H1C, 0);
    }

    // 3) support2 = relu(x) @ W2   [NT,256]x[256,128] -> bufA
    sgemm(bufX, W2, bufA, nullptr, M, H1C, H2C, 0, 1, 0);

    // 4) seq init (b2 + raw), spmm2 scatter into seq (embed part)
    {
        size_t tot = NT * (size_t)DSEQ;
        init_seq<<<8192, 256>>>(seq, b2, raw, tot);
        long long warps = (long long)Tt * Ee;
        long long blocks = (warps * 32 + 255) / 256;
        spmm_scatter<<<(unsigned)blocks, 256>>>(bufA, erow, ecol, ew, seq, H2C, H2C, DSEQ, 1);
    }

    // 5) xg0 = seq @ Wih0^T + bih0   [NT,148]x[148,1024]
    sgemm(seq, Wih0, xg, bih0, M, DSEQ, G4, 1, 0, 0);

    // 6) LSTM layer 0 -> h_seq0 = bufX (reused)
    for (int t = 0; t < Tt; t++) {
        if (t == 0) {
            lstm_update<<<upd_blocks, 256>>>(xg, nullptr, bhh0, cst, hst, bufX, 0);
        } else {
            sgemm(hst, Whh0, R, bhh0, Nn, HID, G4, 1, 0, 0);
            lstm_update<<<upd_blocks, 256>>>(xg, R, bhh0, cst, hst, bufX, t);
        }
    }

    // 7) xg1 = h_seq0 @ Wih1^T + bih1   [NT,256]x[256,1024]
    sgemm(bufX, Wih1, xg, bih1, M, HID, G4, 1, 0, 0);

    // 8) LSTM layer 1 -> h_seq1 = bufA (reused)
    for (int t = 0; t < Tt; t++) {
        if (t == 0) {
            lstm_update<<<upd_blocks, 256>>>(xg, nullptr, bhh1, cst, hst, bufA, 0);
        } else {
            sgemm(hst, Whh1, R, bhh1, Nn, HID, G4, 1, 0, 0);
            lstm_update<<<upd_blocks, 256>>>(xg, R, bhh1, cst, hst, bufA, t);
        }
    }

    // 9) attention pooling over time
    attention_pool<<<Nn, HID>>>(bufA, att_w, att_b, pooled);

    // 10) z = relu(pooled @ fcn_w + fcn_b)   [30000,256]x[256,128]
    sgemm(pooled, fcn_w, z, fcn_b, Nn, HID, 128, 0, 0, 1);

    // 11) out = z @ out_w + out_b   [30000,128]x[128,64]
    sgemm(z, out_w, out, out_b, Nn, 128, OUTC, 0, 0, 0);
}

// round 3
// speedup vs baseline: 2.5922x; 1.2912x over previous
#include <cuda_runtime.h>
#include <cuda_bf16.h>
#include <math.h>
#include <stdint.h>

// ---------------- problem constants ----------------
constexpr int Tt   = 12;
constexpr int Nn   = 30000;
constexpr int Ee   = 480000;
constexpr int FIN  = 128;
constexpr int H1C  = 256;
constexpr int H2C  = 128;
constexpr int RAWC = 20;
constexpr int HID  = 256;
constexpr int OUTC = 64;
constexpr int DSEQ = H2C + RAWC;   // 148
constexpr int G4   = 4 * HID;      // 1024
constexpr size_t NT = (size_t)Nn * Tt;  // 360000

// ---------------- scratch ----------------
__device__ float g_bufA[NT * 256];
__device__ float g_bufX[NT * 256];
__device__ float g_seq [NT * DSEQ];
__device__ float g_xg  [NT * (size_t)G4];
__device__ float g_R   [(size_t)Nn * G4];
__device__ float g_h   [(size_t)Nn * HID];
__device__ float g_c   [(size_t)Nn * HID];
__device__ float g_pool[(size_t)Nn * HID];
__device__ float g_z   [(size_t)Nn * 128];

// =====================================================================
// Tensor-core GEMM: bf16 3-term split (hi*hi + lo*hi + hi*lo), fp32 acc.
// C[M,Nc] = op(A)[M,K] * B + bias; btrans=1 -> B stored [Nc,K] (W layout).
// Block 128x128, K-tile 32, 512 threads = 16 warps (4m x 4n), warp 32x32.
// Requires Nc % 128 == 0, K % 4 == 0.
// =====================================================================
#define PITCH 40   // bf16 elements per smem row (32 + 8 pad) -> conflict-free ldmatrix

__device__ __forceinline__ uint32_t sptr(const void* p) {
    return (uint32_t)__cvta_generic_to_shared(p);
}

__device__ __forceinline__ void ldsm4(uint32_t& r0, uint32_t& r1, uint32_t& r2, uint32_t& r3, uint32_t a) {
    asm volatile("ldmatrix.sync.aligned.m8n8.x4.shared.b16 {%0,%1,%2,%3}, [%4];"
                 : "=r"(r0), "=r"(r1), "=r"(r2), "=r"(r3) : "r"(a));
}
__device__ __forceinline__ void ldsm2(uint32_t& r0, uint32_t& r1, uint32_t a) {
    asm volatile("ldmatrix.sync.aligned.m8n8.x2.shared.b16 {%0,%1}, [%2];"
                 : "=r"(r0), "=r"(r1) : "r"(a));
}
__device__ __forceinline__ void mma_bf16(float* c, const uint32_t* a, const uint32_t* b) {
    asm volatile("mma.sync.aligned.m16n8k16.row.col.f32.bf16.bf16.f32 "
                 "{%0,%1,%2,%3}, {%4,%5,%6,%7}, {%8,%9}, {%0,%1,%2,%3};"
                 : "+f"(c[0]), "+f"(c[1]), "+f"(c[2]), "+f"(c[3])
                 : "r"(a[0]), "r"(a[1]), "r"(a[2]), "r"(a[3]), "r"(b[0]), "r"(b[1]));
}

__global__ void __launch_bounds__(512) mma_gemm_kernel(
    const float* __restrict__ A, const float* __restrict__ B,
    float* __restrict__ C, const float* __restrict__ bias,
    int M, int K, int Nc, int btrans, int relu_a, int relu_c)
{
    __shared__ __nv_bfloat16 As_hi[128 * PITCH];
    __shared__ __nv_bfloat16 As_lo[128 * PITCH];
    __shared__ __nv_bfloat16 Bs_hi[128 * PITCH];
    __shared__ __nv_bfloat16 Bs_lo[128 * PITCH];

    const int tid  = threadIdx.x;
    const int lane = tid & 31;
    const int warp = tid >> 5;
    const int warp_m = (warp >> 2) << 5;  // 0,32,64,96
    const int warp_n = (warp & 3) << 5;   // 0,32,64,96
    const int brow = blockIdx.y * 128;
    const int bcol = blockIdx.x * 128;

    float acc[2][4][4];
#pragma unroll
    for (int i = 0; i < 2; i++)
#pragma unroll
        for (int j = 0; j < 4; j++)
#pragma unroll
            for (int v = 0; v < 4; v++) acc[i][j][v] = 0.f;

    // load mappings (512 threads)
    const int a_row = tid >> 2;          // 0..127
    const int a_k   = (tid & 3) << 3;    // 0,8,16,24
    const int t_k   = tid >> 4;          // 0..31 (btrans=0 B loads)
    const int t_n   = (tid & 15) << 3;   // 0..120

    // ldmatrix addresses (per-thread, constant across k-tiles except k offset)
    const int la = lane & 15;
    const int a_lrow = (lane & 7) + ((lane >> 3) & 1) * 8;  // row within 16
    const int a_lcol = (lane >> 4) * 8;                     // 0 or 8
    const int b_lrow = la & 7;
    const int b_lcol = (la >> 3) * 8;

    for (int k0 = 0; k0 < K; k0 += 32) {
        // ---- load A tile (128x32 fp32 -> split bf16) ----
#pragma unroll
        for (int q = 0; q < 2; q++) {
            int gk = k0 + a_k + q * 4;
            int gr = brow + a_row;
            float4 v = make_float4(0.f, 0.f, 0.f, 0.f);
            if (gr < M && gk < K)
                v = *reinterpret_cast<const float4*>(&A[(size_t)gr * K + gk]);
            if (relu_a) {
                v.x = fmaxf(v.x, 0.f); v.y = fmaxf(v.y, 0.f);
                v.z = fmaxf(v.z, 0.f); v.w = fmaxf(v.w, 0.f);
            }
            float vv[4] = {v.x, v.y, v.z, v.w};
            int sbase = a_row * PITCH + a_k + q * 4;
#pragma unroll
            for (int e = 0; e < 4; e++) {
                __nv_bfloat16 hi = __float2bfloat16(vv[e]);
                As_hi[sbase + e] = hi;
                As_lo[sbase + e] = __float2bfloat16(vv[e] - __bfloat162float(hi));
            }
        }
        // ---- load B tile into Bs[n][k] ----
        if (btrans) {
            // B stored [Nc,K]: rows are n, contiguous k (coalesced)
#pragma unroll
            for (int q = 0; q < 2; q++) {
                int gk = k0 + a_k + q * 4;
                int gn = bcol + a_row;
                float4 v = make_float4(0.f, 0.f, 0.f, 0.f);
                if (gk < K)
                    v = *reinterpret_cast<const float4*>(&B[(size_t)gn * K + gk]);
                float vv[4] = {v.x, v.y, v.z, v.w};
                int sbase = a_row * PITCH + a_k + q * 4;
#pragma unroll
                for (int e = 0; e < 4; e++) {
                    __nv_bfloat16 hi = __float2bfloat16(vv[e]);
                    Bs_hi[sbase + e] = hi;
                    Bs_lo[sbase + e] = __float2bfloat16(vv[e] - __bfloat162float(hi));
                }
            }
        } else {
            // B stored [K,Nc]: read rows of n (coalesced), write transposed
#pragma unroll
            for (int q = 0; q < 2; q++) {
                int gk = k0 + t_k;
                int gn = bcol + t_n + q * 4;
                float4 v = make_float4(0.f, 0.f, 0.f, 0.f);
                if (gk < K)
                    v = *reinterpret_cast<const float4*>(&B[(size_t)gk * Nc + gn]);
                float vv[4] = {v.x, v.y, v.z, v.w};
#pragma unroll
                for (int e = 0; e < 4; e++) {
                    int n = t_n + q * 4 + e;
                    __nv_bfloat16 hi = __float2bfloat16(vv[e]);
                    Bs_hi[n * PITCH + t_k] = hi;
                    Bs_lo[n * PITCH + t_k] = __float2bfloat16(vv[e] - __bfloat162float(hi));
                }
            }
        }
        __syncthreads();

        // ---- compute: 2 k16 steps, 3 passes each ----
#pragma unroll
        for (int s = 0; s < 2; s++) {
            int kb = s * 16;
            uint32_t a_hi[2][4], a_lo[2][4], b_hi[4][2], b_lo[4][2];
#pragma unroll
            for (int mi = 0; mi < 2; mi++) {
                uint32_t ad = sptr(&As_hi[(warp_m + mi * 16 + a_lrow) * PITCH + kb + a_lcol]);
                ldsm4(a_hi[mi][0], a_hi[mi][1], a_hi[mi][2], a_hi[mi][3], ad);
            }
#pragma unroll
            for (int ni = 0; ni < 4; ni++) {
                uint32_t bd = sptr(&Bs_hi[(warp_n + ni * 8 + b_lrow) * PITCH + kb + b_lcol]);
                ldsm2(b_hi[ni][0], b_hi[ni][1], bd);
            }
#pragma unroll
            for (int mi = 0; mi < 2; mi++)
#pragma unroll
                for (int ni = 0; ni < 4; ni++) mma_bf16(acc[mi][ni], a_hi[mi], b_hi[ni]);

#pragma unroll
            for (int mi = 0; mi < 2; mi++) {
                uint32_t ad = sptr(&As_lo[(warp_m + mi * 16 + a_lrow) * PITCH + kb + a_lcol]);
                ldsm4(a_lo[mi][0], a_lo[mi][1], a_lo[mi][2], a_lo[mi][3], ad);
            }
#pragma unroll
            for (int mi = 0; mi < 2; mi++)
#pragma unroll
                for (int ni = 0; ni < 4; ni++) mma_bf16(acc[mi][ni], a_lo[mi], b_hi[ni]);

#pragma unroll
            for (int ni = 0; ni < 4; ni++) {
                uint32_t bd = sptr(&Bs_lo[(warp_n + ni * 8 + b_lrow) * PITCH + kb + b_lcol]);
                ldsm2(b_lo[ni][0], b_lo[ni][1], bd);
            }
#pragma unroll
            for (int mi = 0; mi < 2; mi++)
#pragma unroll
                for (int ni = 0; ni < 4; ni++) mma_bf16(acc[mi][ni], a_hi[mi], b_lo[ni]);
        }
        __syncthreads();
    }

    // ---- epilogue ----
#pragma unroll
    for (int mi = 0; mi < 2; mi++) {
#pragma unroll
        for (int ni = 0; ni < 4; ni++) {
            int n0 = bcol + warp_n + ni * 8 + (lane & 3) * 2;
            float bx = bias ? bias[n0] : 0.f;
            float by = bias ? bias[n0 + 1] : 0.f;
            int m0 = brow + warp_m + mi * 16 + (lane >> 2);
#pragma unroll
            for (int h = 0; h < 2; h++) {
                int m = m0 + h * 8;
                if (m >= M) continue;
                float2 v;
                v.x = acc[mi][ni][h * 2 + 0] + bx;
                v.y = acc[mi][ni][h * 2 + 1] + by;
                if (relu_c) { v.x = fmaxf(v.x, 0.f); v.y = fmaxf(v.y, 0.f); }
                *reinterpret_cast<float2*>(&C[(size_t)m * Nc + n0]) = v;
            }
        }
    }
}

// ---------------- fallback tiled fp32 GEMM (small N: final out gemm) ----------------
template<int BM, int BN, int BK, int TM, int TN>
__global__ void sgemm_kernel(const float* __restrict__ A, const float* __restrict__ B,
                             float* __restrict__ C, const float* __restrict__ bias,
                             int M, int K, int Nc,
                             int btrans, int relu_a, int relu_c)
{
    __shared__ float As[BK][BM];
    __shared__ float Bs[BK][BN];
    const int tid = threadIdx.x;
    const int brow = blockIdx.y * BM;
    const int bcol = blockIdx.x * BN;
    const int trow = (tid / (BN / TN)) * TM;
    const int tcol = (tid % (BN / TN)) * TN;

    float acc[TM][TN];
#pragma unroll
    for (int i = 0; i < TM; i++)
#pragma unroll
        for (int j = 0; j < TN; j++) acc[i][j] = 0.f;

    for (int k0 = 0; k0 < K; k0 += BK) {
#pragma unroll
        for (int i = 0; i < (BM * BK) / 256; i++) {
            int l = tid + i * 256;
            int m = l / BK, k = l % BK;
            int gr = brow + m, gk = k0 + k;
            float v = 0.f;
            if (gr < M && gk < K) v = A[(size_t)gr * K + gk];
            if (relu_a) v = fmaxf(v, 0.f);
            As[k][m] = v;
        }
        if (!btrans) {
#pragma unroll
            for (int i = 0; i < (BK * BN) / 256; i++) {
                int l = tid + i * 256;
                int k = l / BN, n = l % BN;
                int gk = k0 + k, gn = bcol + n;
                float v = 0.f;
                if (gk < K && gn < Nc) v = B[(size_t)gk * Nc + gn];
                Bs[k][n] = v;
            }
        } else {
#pragma unroll
            for (int i = 0; i < (BK * BN) / 256; i++) {
                int l = tid + i * 256;
                int n = l / BK, k = l % BK;
                int gk = k0 + k, gn = bcol + n;
                float v = 0.f;
                if (gk < K && gn < Nc) v = B[(size_t)gn * K + gk];
                Bs[k][n] = v;
            }
        }
        __syncthreads();
#pragma unroll
        for (int k = 0; k < BK; k++) {
            float ar[TM], br[TN];
#pragma unroll
            for (int i = 0; i < TM; i++) ar[i] = As[k][trow + i];
#pragma unroll
            for (int j = 0; j < TN; j++) br[j] = Bs[k][tcol + j];
#pragma unroll
            for (int i = 0; i < TM; i++)
#pragma unroll
                for (int j = 0; j < TN; j++) acc[i][j] = fmaf(ar[i], br[j], acc[i][j]);
        }
        __syncthreads();
    }
#pragma unroll
    for (int i = 0; i < TM; i++) {
        int gr = brow + trow + i;
        if (gr >= M) continue;
#pragma unroll
        for (int j = 0; j < TN; j++) {
            int gn = bcol + tcol + j;
            if (gn >= Nc) continue;
            float v = acc[i][j];
            if (bias) v += bias[gn];
            if (relu_c) v = fmaxf(v, 0.f);
            C[(size_t)gr * Nc + gn] = v;
        }
    }
}

static inline void gemm(const float* A, const float* B, float* C, const float* bias,
                        int M, int K, int Nc, int btrans, int relu_a, int relu_c)
{
    if ((Nc % 128) == 0 && (K % 4) == 0) {
        dim3 grid(Nc / 128, (M + 127) / 128);
        mma_gemm_kernel<<<grid, 512>>>(A, B, C, bias, M, K, Nc, btrans, relu_a, relu_c);
    } else {
        dim3 grid((Nc + 63) / 64, (M + 63) / 64);
        sgemm_kernel<64, 64, 16, 4, 4><<<grid, 256>>>(A, B, C, bias, M, K, Nc, btrans, relu_a, relu_c);
    }
}

// ---------------- SpMM scatter ----------------
__global__ void spmm_scatter(const float* __restrict__ src,
                             const int* __restrict__ erow, const int* __restrict__ ecol,
                             const float* __restrict__ ew,
                             float* __restrict__ dst,
                             int ncols, int src_ld, int dst_ld, int dst_layout)
{
    long long warp = ((long long)blockIdx.x * blockDim.x + threadIdx.x) >> 5;
    int lane = threadIdx.x & 31;
    if (warp >= (long long)Tt * Ee) return;
    int t = (int)(warp / Ee);
    int e = (int)(warp % Ee);
    size_t eoff = (size_t)t * Ee + e;
    int r = erow[eoff];
    int c = ecol[eoff];
    float w = ew[eoff];
    const float* s = src + ((size_t)t * Nn + c) * src_ld;
    size_t doff = (dst_layout == 0) ? ((size_t)t * Nn + r) * (size_t)dst_ld
                                    : ((size_t)r * Tt + t) * (size_t)dst_ld;
    float* d = dst + doff;
    for (int j = lane; j < ncols; j += 32) atomicAdd(&d[j], w * s[j]);
}

// ---------------- init kernels ----------------
__global__ void init_bias_bcast(float* __restrict__ dst, const float* __restrict__ bias,
                                int C, size_t total)
{
    size_t stride = (size_t)gridDim.x * blockDim.x;
    for (size_t i = (size_t)blockIdx.x * blockDim.x + threadIdx.x; i < total; i += stride)
        dst[i] = bias[i % C];
}

__global__ void init_seq(float* __restrict__ seq, const float* __restrict__ b2,
                         const float* __restrict__ raw, size_t total)
{
    size_t stride = (size_t)gridDim.x * blockDim.x;
    for (size_t i = (size_t)blockIdx.x * blockDim.x + threadIdx.x; i < total; i += stride) {
        int c = (int)(i % DSEQ);
        size_t nt = i / DSEQ;
        int t = (int)(nt % Tt);
        size_t n = nt / Tt;
        seq[i] = (c < H2C) ? b2[c]
                           : raw[(size_t)t * Nn * RAWC + n * RAWC + (c - H2C)];
    }
}

// ---------------- LSTM pointwise update ----------------
__device__ __forceinline__ float sigmoidf_(float x) { return 1.f / (1.f + expf(-x)); }

__global__ void lstm_update(const float* __restrict__ xg,
                            const float* __restrict__ R,
                            const float* __restrict__ bhh,
                            float* __restrict__ cst, float* __restrict__ hst,
                            float* __restrict__ hseq, int t)
{
    size_t idx = (size_t)blockIdx.x * blockDim.x + threadIdx.x;
    if (idx >= (size_t)Nn * HID) return;
    size_t n = idx / HID;
    int j = (int)(idx % HID);
    const float* xr = xg + ((size_t)n * Tt + t) * G4;
    float ri, rf, rg, ro;
    if (R) {
        const float* rr = R + n * (size_t)G4;
        ri = rr[j]; rf = rr[HID + j]; rg = rr[2 * HID + j]; ro = rr[3 * HID + j];
    } else {
        ri = bhh[j]; rf = bhh[HID + j]; rg = bhh[2 * HID + j]; ro = bhh[3 * HID + j];
    }
    float gi = xr[j]           + ri;
    float gf = xr[HID + j]     + rf;
    float gg = xr[2 * HID + j] + rg;
    float go = xr[3 * HID + j] + ro;
    float cprev = (R) ? cst[idx] : 0.f;
    float cn = sigmoidf_(gf) * cprev + sigmoidf_(gi) * tanhf(gg);
    float hn = sigmoidf_(go) * tanhf(cn);
    cst[idx] = cn;
    hst[idx] = hn;
    hseq[((size_t)n * Tt + t) * HID + j] = hn;
}

// ---------------- attention pooling ----------------
__global__ void attention_pool(const float* __restrict__ hseq,
                               const float* __restrict__ att_w,
                               const float* __restrict__ att_b,
                               float* __restrict__ pooled)
{
    __shared__ float hs[Tt * HID];
    __shared__ float aw[HID];
    __shared__ float red[HID];
    __shared__ float sc[Tt];
    int n = blockIdx.x;
    int tid = threadIdx.x;
    const float* base = hseq + (size_t)n * Tt * HID;
#pragma unroll
    for (int i = 0; i < Tt; i++) hs[i * HID + tid] = base[i * HID + tid];
    aw[tid] = att_w[tid];
    __syncthreads();
    float ab = att_b[0];
    for (int t = 0; t < Tt; t++) {
        red[tid] = hs[t * HID + tid] * aw[tid];
        __syncthreads();
        for (int s = HID / 2; s > 0; s >>= 1) {
            if (tid < s) red[tid] += red[tid + s];
            __syncthreads();
        }
        if (tid == 0) sc[t] = red[0] + ab;
        __syncthreads();
    }
    float mx = -1e30f;
#pragma unroll
    for (int t = 0; t < Tt; t++) mx = fmaxf(mx, sc[t]);
    float a[Tt], sum = 0.f;
#pragma unroll
    for (int t = 0; t < Tt; t++) { a[t] = expf(sc[t] - mx); sum += a[t]; }
    float p = 0.f;
#pragma unroll
    for (int t = 0; t < Tt; t++) p += a[t] * hs[t * HID + tid];
    pooled[(size_t)n * HID + tid] = p / sum;
}

// ---------------- launch ----------------
extern "C" void kernel_launch(void* const* d_in, const int* in_sizes, int n_in,
                              void* d_out, int out_size)
{
    const float* nodes = (const float*)d_in[0];
    const int*   erow  = (const int*)  d_in[1];
    const int*   ecol  = (const int*)  d_in[2];
    const float* ew    = (const float*)d_in[3];
    const float* raw   = (const float*)d_in[4];
    const float* W1    = (const float*)d_in[5];
    const float* b1    = (const float*)d_in[6];
    const float* W2    = (const float*)d_in[7];
    const float* b2    = (const float*)d_in[8];
    const float* Wih0  = (const float*)d_in[9];
    const float* Whh0  = (const float*)d_in[10];
    const float* bih0  = (const float*)d_in[11];
    const float* bhh0  = (const float*)d_in[12];
    const float* Wih1  = (const float*)d_in[13];
    const float* Whh1  = (const float*)d_in[14];
    const float* bih1  = (const float*)d_in[15];
    const float* bhh1  = (const float*)d_in[16];
    const float* att_w = (const float*)d_in[17];
    const float* att_b = (const float*)d_in[18];
    const float* fcn_w = (const float*)d_in[19];
    const float* fcn_b = (const float*)d_in[20];
    const float* out_w = (const float*)d_in[21];
    const float* out_b = (const float*)d_in[22];
    float* out = (float*)d_out;

    float *bufA, *bufX, *seq, *xg, *R, *hst, *cst, *pooled, *z;
    cudaGetSymbolAddress((void**)&bufA,   g_bufA);
    cudaGetSymbolAddress((void**)&bufX,   g_bufX);
    cudaGetSymbolAddress((void**)&seq,    g_seq);
    cudaGetSymbolAddress((void**)&xg,     g_xg);
    cudaGetSymbolAddress((void**)&R,      g_R);
    cudaGetSymbolAddress((void**)&hst,    g_h);
    cudaGetSymbolAddress((void**)&cst,    g_c);
    cudaGetSymbolAddress((void**)&pooled, g_pool);
    cudaGetSymbolAddress((void**)&z,      g_z);

    const int M = (int)NT;
    const int upd_blocks = (int)(((size_t)Nn * HID + 255) / 256);

    // 1) support1 = nodes @ W1   [NT,128]x[128,256]
    gemm(nodes, W1, bufA, nullptr, M, FIN, H1C, 0, 0, 0);

    // 2) x := b1, scatter-add spmm(support1); relu folded into next gemm
    {
        size_t tot = NT * (size_t)H1C;
        init_bias_bcast<<<8192, 256>>>(bufX, b1, H1C, tot);
        long long warps = (long long)Tt * Ee;
        long long blocks = (warps * 32 + 255) / 256;
        spmm_scatter<<<(unsigned)blocks, 256>>>(bufA, erow, ecol, ew, bufX, H1C, H1C, H1C, 0);
    }

    // 3) support2 = relu(x) @ W2   [NT,256]x[256,128]
    gemm(bufX, W2, bufA, nullptr, M, H1C, H2C, 0, 1, 0);

    // 4) seq init, spmm2 scatter into seq
    {
        size_t tot = NT * (size_t)DSEQ;
        init_seq<<<8192, 256>>>(seq, b2, raw, tot);
        long long warps = (long long)Tt * Ee;
        long long blocks = (warps * 32 + 255) / 256;
        spmm_scatter<<<(unsigned)blocks, 256>>>(bufA, erow, ecol, ew, seq, H2C, H2C, DSEQ, 1);
    }

    // 5) xg0 = seq @ Wih0^T + bih0   [NT,148]x[148,1024]
    gemm(seq, Wih0, xg, bih0, M, DSEQ, G4, 1, 0, 0);

    // 6) LSTM layer 0 -> h_seq0 = bufX
    for (int t = 0; t < Tt; t++) {
        if (t == 0) {
            lstm_update<<<upd_blocks, 256>>>(xg, nullptr, bhh0, cst, hst, bufX, 0);
        } else {
            gemm(hst, Whh0, R, bhh0, Nn, HID, G4, 1, 0, 0);
            lstm_update<<<upd_blocks, 256>>>(xg, R, bhh0, cst, hst, bufX, t);
        }
    }

    // 7) xg1 = h_seq0 @ Wih1^T + bih1   [NT,256]x[256,1024]
    gemm(bufX, Wih1, xg, bih1, M, HID, G4, 1, 0, 0);

    // 8) LSTM layer 1 -> h_seq1 = bufA
    for (int t = 0; t < Tt; t++) {
        if (t == 0) {
            lstm_update<<<upd_blocks, 256>>>(xg, nullptr, bhh1, cst, hst, bufA, 0);
        } else {
            gemm(hst, Whh1, R, bhh1, Nn, HID, G4, 1, 0, 0);
            lstm_update<<<upd_blocks, 256>>>(xg, R, bhh1, cst, hst, bufA, t);
        }
    }

    // 9) attention pooling
    attention_pool<<<Nn, HID>>>(bufA, att_w, att_b, pooled);

    // 10) z = relu(pooled @ fcn_w + fcn_b)
    gemm(pooled, fcn_w, z, fcn_b, Nn, HID, 128, 0, 0, 1);

    // 11) out = z @ out_w + out_b   (Nc=64 -> fp32 fallback)
    gemm(z, out_w, out, out_b, Nn, 128, OUTC, 0, 0, 0);
}

// round 4
// speedup vs baseline: 3.8419x; 1.4821x over previous
#include <cuda_runtime.h>
#include <cuda_bf16.h>
#include <math.h>
#include <stdint.h>

// ---------------- problem constants ----------------
constexpr int Tt   = 12;
constexpr int Nn   = 30000;
constexpr int Ee   = 480000;
constexpr int FIN  = 128;
constexpr int H1C  = 256;
constexpr int H2C  = 128;
constexpr int RAWC = 20;
constexpr int HID  = 256;
constexpr int OUTC = 64;
constexpr int DSEQ = H2C + RAWC;   // 148
constexpr int DSEQP= 160;          // padded for MMA
constexpr int G4   = 4 * HID;      // 1024
constexpr size_t NT = (size_t)Nn * Tt;  // 360000

// weight split buffer offsets (elements)
constexpr size_t OFF_W1T  = 0;                        // [256,128]
constexpr size_t OFF_W2T  = 32768;                    // [128,256]
constexpr size_t OFF_WIH0 = 65536;                    // [1024,160]
constexpr size_t OFF_WHH0 = 229376;                   // [1024,256]
constexpr size_t OFF_WIH1 = 491520;                   // [1024,256]
constexpr size_t OFF_WHH1 = 753664;                   // [1024,256]
constexpr size_t OFF_FCNT = 1015808;                  // [128,256]
constexpr size_t WSPLIT_SZ= 1048576;

// ---------------- scratch ----------------
__device__ float g_bufA[NT * 256];
__device__ float g_bufX[NT * 256];
__device__ float g_seq [NT * DSEQ];
__device__ float g_xg  [NT * (size_t)G4];
__device__ float g_R   [(size_t)Nn * G4];
__device__ float g_h   [(size_t)Nn * HID];
__device__ float g_c   [(size_t)Nn * HID];
__device__ float g_z   [(size_t)Nn * 128];
__device__ __nv_bfloat16 g_ahi[NT * 256];
__device__ __nv_bfloat16 g_alo[NT * 256];
__device__ __nv_bfloat16 g_hhi[(size_t)Nn * HID];
__device__ __nv_bfloat16 g_hlo[(size_t)Nn * HID];
__device__ __nv_bfloat16 g_phi[(size_t)Nn * HID];
__device__ __nv_bfloat16 g_plo[(size_t)Nn * HID];
__device__ __nv_bfloat16 g_whi[WSPLIT_SZ];
__device__ __nv_bfloat16 g_wlo[WSPLIT_SZ];

// ---------------- helpers ----------------
__device__ __forceinline__ uint32_t sptr(const void* p) {
    return (uint32_t)__cvta_generic_to_shared(p);
}
__device__ __forceinline__ void ldsm4(uint32_t& r0, uint32_t& r1, uint32_t& r2, uint32_t& r3, uint32_t a) {
    asm volatile("ldmatrix.sync.aligned.m8n8.x4.shared.b16 {%0,%1,%2,%3}, [%4];"
                 : "=r"(r0), "=r"(r1), "=r"(r2), "=r"(r3) : "r"(a));
}
__device__ __forceinline__ void ldsm2(uint32_t& r0, uint32_t& r1, uint32_t a) {
    asm volatile("ldmatrix.sync.aligned.m8n8.x2.shared.b16 {%0,%1}, [%2];"
                 : "=r"(r0), "=r"(r1) : "r"(a));
}
__device__ __forceinline__ void mma_bf16(float* c, const uint32_t* a, const uint32_t* b) {
    asm volatile("mma.sync.aligned.m16n8k16.row.col.f32.bf16.bf16.f32 "
                 "{%0,%1,%2,%3}, {%4,%5,%6,%7}, {%8,%9}, {%0,%1,%2,%3};"
                 : "+f"(c[0]), "+f"(c[1]), "+f"(c[2]), "+f"(c[3])
                 : "r"(a[0]), "r"(a[1]), "r"(a[2]), "r"(a[3]), "r"(b[0]), "r"(b[1]));
}
__device__ __forceinline__ void cpasync16(void* dst, const void* src, bool pred) {
    int sz = pred ? 16 : 0;
    asm volatile("cp.async.ca.shared.global [%0], [%1], 16, %2;"
                 :: "r"(sptr(dst)), "l"(src), "r"(sz));
}

// =====================================================================
// Tensor-core GEMM on pre-split bf16 operands (hi*hi + lo*hi + hi*lo).
// A: [M, K] hi/lo bf16, row-major, K = lda (multiple of 32).
// B: [Nc, K] hi/lo bf16, row-major (i.e., B^T layout). Nc % 128 == 0.
// C fp32 [M, Nc], + bias, optional relu.
// Block 128x128, k-tile 32, 512 threads, 2-stage cp.async pipeline.
// =====================================================================
#define PITCH 40
#define BUFE  (128 * PITCH)   // 5120 bf16 per buffer

__global__ void __launch_bounds__(512) mma_gemm_bf16(
    const __nv_bfloat16* __restrict__ Ahi, const __nv_bfloat16* __restrict__ Alo,
    const __nv_bfloat16* __restrict__ Bhi, const __nv_bfloat16* __restrict__ Blo,
    float* __restrict__ C, const float* __restrict__ bias,
    int M, int lda, int Nc, int relu_c)
{
    extern __shared__ __nv_bfloat16 smem[];  // 2 stages x 4 buffers x BUFE

    const int tid  = threadIdx.x;
    const int lane = tid & 31;
    const int warp = tid >> 5;
    const int warp_m = (warp >> 2) << 5;
    const int warp_n = (warp & 3) << 5;
    const int brow = blockIdx.y * 128;
    const int bcol = blockIdx.x * 128;

    float acc[2][4][4];
#pragma unroll
    for (int i = 0; i < 2; i++)
#pragma unroll
        for (int j = 0; j < 4; j++)
#pragma unroll
            for (int v = 0; v < 4; v++) acc[i][j][v] = 0.f;

    const int l_row = tid >> 2;          // 0..127
    const int l_kc  = (tid & 3) << 3;    // 0,8,16,24

    const int gr  = brow + l_row;
    const bool okA = (gr < M);
    const int grc = okA ? gr : 0;
    const int gn  = bcol + l_row;

    const int a_lrow = (lane & 7) + ((lane >> 3) & 1) * 8;
    const int a_lcol = (lane >> 4) * 8;
    const int b_lrow = lane & 7;
    const int b_lcol = ((lane & 15) >> 3) * 8;

    auto load_stage = [&](int s, int k0) {
        __nv_bfloat16* base = smem + s * 4 * BUFE;
        size_t aoff = (size_t)grc * lda + k0 + l_kc;
        size_t boff = (size_t)gn  * lda + k0 + l_kc;
        int so = l_row * PITCH + l_kc;
        cpasync16(base + 0 * BUFE + so, Ahi + aoff, okA);
        cpasync16(base + 1 * BUFE + so, Alo + aoff, okA);
        cpasync16(base + 2 * BUFE + so, Bhi + boff, true);
        cpasync16(base + 3 * BUFE + so, Blo + boff, true);
    };

    auto compute = [&](int s) {
        __nv_bfloat16* As_hi = smem + (s * 4 + 0) * BUFE;
        __nv_bfloat16* As_lo = smem + (s * 4 + 1) * BUFE;
        __nv_bfloat16* Bs_hi = smem + (s * 4 + 2) * BUFE;
        __nv_bfloat16* Bs_lo = smem + (s * 4 + 3) * BUFE;
#pragma unroll
        for (int st = 0; st < 2; st++) {
            int kb = st * 16;
            uint32_t a_hi[2][4], a_lo[2][4], b[4][2];
#pragma unroll
            for (int mi = 0; mi < 2; mi++) {
                uint32_t ad = sptr(&As_hi[(warp_m + mi * 16 + a_lrow) * PITCH + kb + a_lcol]);
                ldsm4(a_hi[mi][0], a_hi[mi][1], a_hi[mi][2], a_hi[mi][3], ad);
            }
#pragma unroll
            for (int ni = 0; ni < 4; ni++) {
                uint32_t bd = sptr(&Bs_hi[(warp_n + ni * 8 + b_lrow) * PITCH + kb + b_lcol]);
                ldsm2(b[ni][0], b[ni][1], bd);
            }
#pragma unroll
            for (int mi = 0; mi < 2; mi++)
#pragma unroll
                for (int ni = 0; ni < 4; ni++) mma_bf16(acc[mi][ni], a_hi[mi], b[ni]);
#pragma unroll
            for (int mi = 0; mi < 2; mi++) {
                uint32_t ad = sptr(&As_lo[(warp_m + mi * 16 + a_lrow) * PITCH + kb + a_lcol]);
                ldsm4(a_lo[mi][0], a_lo[mi][1], a_lo[mi][2], a_lo[mi][3], ad);
            }
#pragma unroll
            for (int mi = 0; mi < 2; mi++)
#pragma unroll
                for (int ni = 0; ni < 4; ni++) mma_bf16(acc[mi][ni], a_lo[mi], b[ni]);
#pragma unroll
            for (int ni = 0; ni < 4; ni++) {
                uint32_t bd = sptr(&Bs_lo[(warp_n + ni * 8 + b_lrow) * PITCH + kb + b_lcol]);
                ldsm2(b[ni][0], b[ni][1], bd);
            }
#pragma unroll
            for (int mi = 0; mi < 2; mi++)
#pragma unroll
                for (int ni = 0; ni < 4; ni++) mma_bf16(acc[mi][ni], a_hi[mi], b[ni]);
        }
    };

    const int KT = lda >> 5;
    load_stage(0, 0);
    asm volatile("cp.async.commit_group;" ::: "memory");
    for (int kt = 0; kt < KT; kt++) {
        if (kt + 1 < KT) {
            load_stage((kt + 1) & 1, (kt + 1) << 5);
            asm volatile("cp.async.commit_group;" ::: "memory");
            asm volatile("cp.async.wait_group 1;" ::: "memory");
        } else {
            asm volatile("cp.async.wait_group 0;" ::: "memory");
        }
        __syncthreads();
        compute(kt & 1);
        __syncthreads();
    }

    // epilogue
#pragma unroll
    for (int mi = 0; mi < 2; mi++) {
#pragma unroll
        for (int ni = 0; ni < 4; ni++) {
            int n0 = bcol + warp_n + ni * 8 + (lane & 3) * 2;
            float bx = bias ? bias[n0] : 0.f;
            float by = bias ? bias[n0 + 1] : 0.f;
            int m0 = brow + warp_m + mi * 16 + (lane >> 2);
#pragma unroll
            for (int h = 0; h < 2; h++) {
                int m = m0 + h * 8;
                if (m >= M) continue;
                float2 v;
                v.x = acc[mi][ni][h * 2 + 0] + bx;
                v.y = acc[mi][ni][h * 2 + 1] + by;
                if (relu_c) { v.x = fmaxf(v.x, 0.f); v.y = fmaxf(v.y, 0.f); }
                *reinterpret_cast<float2*>(&C[(size_t)m * Nc + n0]) = v;
            }
        }
    }
}

// ---------------- split kernels ----------------
// row-major [R,C] fp32 -> [R,Cp] bf16 hi/lo, zero pad beyond C, optional relu.
// C % 4 == 0, Cp % 4 == 0.
__global__ void split_rows(const float* __restrict__ src,
                           __nv_bfloat16* __restrict__ hi, __nv_bfloat16* __restrict__ lo,
                           long long R, int C, int Cp, int relu)
{
    long long total = R * (Cp >> 2);
    long long stride = (long long)gridDim.x * blockDim.x;
    int gpr = Cp >> 2;
    for (long long g = (long long)blockIdx.x * blockDim.x + threadIdx.x; g < total; g += stride) {
        int gp = (int)(g % gpr);
        long long r = g / gpr;
        int c = gp << 2;
        float4 v = make_float4(0.f, 0.f, 0.f, 0.f);
        if (c < C) v = *reinterpret_cast<const float4*>(&src[r * C + c]);
        if (relu) {
            v.x = fmaxf(v.x, 0.f); v.y = fmaxf(v.y, 0.f);
            v.z = fmaxf(v.z, 0.f); v.w = fmaxf(v.w, 0.f);
        }
        float vv[4] = {v.x, v.y, v.z, v.w};
        __nv_bfloat16 h4[4], l4[4];
#pragma unroll
        for (int e = 0; e < 4; e++) {
            h4[e] = __float2bfloat16(vv[e]);
            l4[e] = __float2bfloat16(vv[e] - __bfloat162float(h4[e]));
        }
        *reinterpret_cast<uint2*>(&hi[r * Cp + c]) = *reinterpret_cast<uint2*>(h4);
        *reinterpret_cast<uint2*>(&lo[r * Cp + c]) = *reinterpret_cast<uint2*>(l4);
    }
}

// [K,Nc] fp32 -> transposed [Nc,K] bf16 hi/lo (small matrices)
__global__ void split_transpose(const float* __restrict__ src,
                                __nv_bfloat16* __restrict__ hi, __nv_bfloat16* __restrict__ lo,
                                int K, int Nc)
{
    int idx = blockIdx.x * blockDim.x + threadIdx.x;
    if (idx >= K * Nc) return;
    int k = idx / Nc, n = idx % Nc;
    float v = src[idx];
    __nv_bfloat16 h = __float2bfloat16(v);
    hi[(size_t)n * K + k] = h;
    lo[(size_t)n * K + k] = __float2bfloat16(v - __bfloat162float(h));
}

// ---------------- fp32 fallback GEMM (final out gemm, Nc=64) ----------------
template<int BM, int BN, int BK, int TM, int TN>
__global__ void sgemm_kernel(const float* __restrict__ A, const float* __restrict__ B,
                             float* __restrict__ C, const float* __restrict__ bias,
                             int M, int K, int Nc)
{
    __shared__ float As[BK][BM];
    __shared__ float Bs[BK][BN];
    const int tid = threadIdx.x;
    const int brow = blockIdx.y * BM;
    const int bcol = blockIdx.x * BN;
    const int trow = (tid / (BN / TN)) * TM;
    const int tcol = (tid % (BN / TN)) * TN;

    float acc[TM][TN];
#pragma unroll
    for (int i = 0; i < TM; i++)
#pragma unroll
        for (int j = 0; j < TN; j++) acc[i][j] = 0.f;

    for (int k0 = 0; k0 < K; k0 += BK) {
#pragma unroll
        for (int i = 0; i < (BM * BK) / 256; i++) {
            int l = tid + i * 256;
            int m = l / BK, k = l % BK;
            int gr = brow + m, gk = k0 + k;
            As[k][m] = (gr < M && gk < K) ? A[(size_t)gr * K + gk] : 0.f;
        }
#pragma unroll
        for (int i = 0; i < (BK * BN) / 256; i++) {
            int l = tid + i * 256;
            int k = l / BN, n = l % BN;
            int gk = k0 + k, gn = bcol + n;
            Bs[k][n] = (gk < K && gn < Nc) ? B[(size_t)gk * Nc + gn] : 0.f;
        }
        __syncthreads();
#pragma unroll
        for (int k = 0; k < BK; k++) {
            float ar[TM], br[TN];
#pragma unroll
            for (int i = 0; i < TM; i++) ar[i] = As[k][trow + i];
#pragma unroll
            for (int j = 0; j < TN; j++) br[j] = Bs[k][tcol + j];
#pragma unroll
            for (int i = 0; i < TM; i++)
#pragma unroll
                for (int j = 0; j < TN; j++) acc[i][j] = fmaf(ar[i], br[j], acc[i][j]);
        }
        __syncthreads();
    }
#pragma unroll
    for (int i = 0; i < TM; i++) {
        int gr = brow + trow + i;
        if (gr >= M) continue;
#pragma unroll
        for (int j = 0; j < TN; j++) {
            int gn = bcol + tcol + j;
            if (gn >= Nc) continue;
            float v = acc[i][j];
            if (bias) v += bias[gn];
            C[(size_t)gr * Nc + gn] = v;
        }
    }
}

// ---------------- SpMM scatter ----------------
__global__ void spmm_scatter(const float* __restrict__ src,
                             const int* __restrict__ erow, const int* __restrict__ ecol,
                             const float* __restrict__ ew,
                             float* __restrict__ dst,
                             int ncols, int src_ld, int dst_ld, int dst_layout)
{
    long long warp = ((long long)blockIdx.x * blockDim.x + threadIdx.x) >> 5;
    int lane = threadIdx.x & 31;
    if (warp >= (long long)Tt * Ee) return;
    int t = (int)(warp / Ee);
    int e = (int)(warp % Ee);
    size_t eoff = (size_t)t * Ee + e;
    int r = erow[eoff];
    int c = ecol[eoff];
    float w = ew[eoff];
    const float* s = src + ((size_t)t * Nn + c) * src_ld;
    size_t doff = (dst_layout == 0) ? ((size_t)t * Nn + r) * (size_t)dst_ld
                                    : ((size_t)r * Tt + t) * (size_t)dst_ld;
    float* d = dst + doff;
    for (int j = lane; j < ncols; j += 32) atomicAdd(&d[j], w * s[j]);
}

// ---------------- init kernels ----------------
__global__ void init_bias_bcast(float* __restrict__ dst, const float* __restrict__ bias,
                                int C, size_t total)
{
    size_t stride = (size_t)gridDim.x * blockDim.x;
    for (size_t i = (size_t)blockIdx.x * blockDim.x + threadIdx.x; i < total; i += stride)
        dst[i] = bias[i % C];
}

__global__ void init_seq(float* __restrict__ seq, const float* __restrict__ b2,
                         const float* __restrict__ raw, size_t total)
{
    size_t stride = (size_t)gridDim.x * blockDim.x;
    for (size_t i = (size_t)blockIdx.x * blockDim.x + threadIdx.x; i < total; i += stride) {
        int c = (int)(i % DSEQ);
        size_t nt = i / DSEQ;
        int t = (int)(nt % Tt);
        size_t n = nt / Tt;
        seq[i] = (c < H2C) ? b2[c]
                           : raw[(size_t)t * Nn * RAWC + n * RAWC + (c - H2C)];
    }
}

// ---------------- LSTM pointwise (fused h-split outputs) ----------------
__device__ __forceinline__ float sigmoidf_(float x) { return 1.f / (1.f + expf(-x)); }

__global__ void lstm_update(const float* __restrict__ xg,
                            const float* __restrict__ R,
                            const float* __restrict__ bhh,
                            float* __restrict__ cst, float* __restrict__ hst,
                            __nv_bfloat16* __restrict__ hhi, __nv_bfloat16* __restrict__ hlo,
                            float* __restrict__ hseq,
                            __nv_bfloat16* __restrict__ ahi, __nv_bfloat16* __restrict__ alo,
                            int write_aseq, int t)
{
    size_t idx = (size_t)blockIdx.x * blockDim.x + threadIdx.x;
    if (idx >= (size_t)Nn * HID) return;
    size_t n = idx / HID;
    int j = (int)(idx % HID);
    const float* xr = xg + ((size_t)n * Tt + t) * G4;
    float ri, rf, rg, ro;
    if (R) {
        const float* rr = R + n * (size_t)G4;
        ri = rr[j]; rf = rr[HID + j]; rg = rr[2 * HID + j]; ro = rr[3 * HID + j];
    } else {
        ri = bhh[j]; rf = bhh[HID + j]; rg = bhh[2 * HID + j]; ro = bhh[3 * HID + j];
    }
    float gi = xr[j]           + ri;
    float gf = xr[HID + j]     + rf;
    float gg = xr[2 * HID + j] + rg;
    float go = xr[3 * HID + j] + ro;
    float cprev = (R) ? cst[idx] : 0.f;
    float cn = sigmoidf_(gf) * cprev + sigmoidf_(gi) * tanhf(gg);
    float hn = sigmoidf_(go) * tanhf(cn);
    cst[idx] = cn;
    hst[idx] = hn;
    __nv_bfloat16 h = __float2bfloat16(hn);
    hhi[idx] = h;
    hlo[idx] = __float2bfloat16(hn - __bfloat162float(h));
    size_t so = ((size_t)n * Tt + t) * HID + j;
    hseq[so] = hn;
    if (write_aseq) {
        ahi[so] = h;
        alo[so] = __float2bfloat16(hn - __bfloat162float(h));
    }
}

// ---------------- attention pooling (writes split pooled) ----------------
__global__ void attention_pool(const float* __restrict__ hseq,
                               const float* __restrict__ att_w,
                               const float* __restrict__ att_b,
                               __nv_bfloat16* __restrict__ phi,
                               __nv_bfloat16* __restrict__ plo)
{
    __shared__ float hs[Tt * HID];
    __shared__ float aw[HID];
    __shared__ float red[HID];
    __shared__ float sc[Tt];
    int n = blockIdx.x;
    int tid = threadIdx.x;
    const float* base = hseq + (size_t)n * Tt * HID;
#pragma unroll
    for (int i = 0; i < Tt; i++) hs[i * HID + tid] = base[i * HID + tid];
    aw[tid] = att_w[tid];
    __syncthreads();
    float ab = att_b[0];
    for (int t = 0; t < Tt; t++) {
        red[tid] = hs[t * HID + tid] * aw[tid];
        __syncthreads();
        for (int s = HID / 2; s > 0; s >>= 1) {
            if (tid < s) red[tid] += red[tid + s];
            __syncthreads();
        }
        if (tid == 0) sc[t] = red[0] + ab;
        __syncthreads();
    }
    float mx = -1e30f;
#pragma unroll
    for (int t = 0; t < Tt; t++) mx = fmaxf(mx, sc[t]);
    float a[Tt], sum = 0.f;
#pragma unroll
    for (int t = 0; t < Tt; t++) { a[t] = expf(sc[t] - mx); sum += a[t]; }
    float p = 0.f;
#pragma unroll
    for (int t = 0; t < Tt; t++) p += a[t] * hs[t * HID + tid];
    p /= sum;
    __nv_bfloat16 h = __float2bfloat16(p);
    phi[(size_t)n * HID + tid] = h;
    plo[(size_t)n * HID + tid] = __float2bfloat16(p - __bfloat162float(h));
}

// ---------------- host-side helpers ----------------
static inline void mma_gemm(const __nv_bfloat16* Ahi, const __nv_bfloat16* Alo,
                            const __nv_bfloat16* Bhi, const __nv_bfloat16* Blo,
                            float* C, const float* bias, int M, int lda, int Nc, int relu_c)
{
    dim3 grid(Nc / 128, (M + 127) / 128);
    size_t shmem = 2 * 4 * BUFE * sizeof(__nv_bfloat16);  // 81920
    mma_gemm_bf16<<<grid, 512, shmem>>>(Ahi, Alo, Bhi, Blo, C, bias, M, lda, Nc, relu_c);
}

extern "C" void kernel_launch(void* const* d_in, const int* in_sizes, int n_in,
                              void* d_out, int out_size)
{
    const float* nodes = (const float*)d_in[0];
    const int*   erow  = (const int*)  d_in[1];
    const int*   ecol  = (const int*)  d_in[2];
    const float* ew    = (const float*)d_in[3];
    const float* raw   = (const float*)d_in[4];
    const float* W1    = (const float*)d_in[5];
    const float* b1    = (const float*)d_in[6];
    const float* W2    = (const float*)d_in[7];
    const float* b2    = (const float*)d_in[8];
    const float* Wih0  = (const float*)d_in[9];
    const float* Whh0  = (const float*)d_in[10];
    const float* bih0  = (const float*)d_in[11];
    const float* bhh0  = (const float*)d_in[12];
    const float* Wih1  = (const float*)d_in[13];
    const float* Whh1  = (const float*)d_in[14];
    const float* bih1  = (const float*)d_in[15];
    const float* bhh1  = (const float*)d_in[16];
    const float* att_w = (const float*)d_in[17];
    const float* att_b = (const float*)d_in[18];
    const float* fcn_w = (const float*)d_in[19];
    const float* fcn_b = (const float*)d_in[20];
    const float* out_w = (const float*)d_in[21];
    const float* out_b = (const float*)d_in[22];
    float* out = (float*)d_out;

    static bool attr_done = false;
    if (!attr_done) {
        cudaFuncSetAttribute(mma_gemm_bf16, cudaFuncAttributeMaxDynamicSharedMemorySize,
                             (int)(2 * 4 * BUFE * sizeof(__nv_bfloat16)));
        attr_done = true;
    }

    float *bufA, *bufX, *seq, *xg, *R, *hst, *cst, *z;
    __nv_bfloat16 *ahi, *alo, *hhi, *hlo, *phi, *plo, *whi, *wlo;
    cudaGetSymbolAddress((void**)&bufA, g_bufA);
    cudaGetSymbolAddress((void**)&bufX, g_bufX);
    cudaGetSymbolAddress((void**)&seq,  g_seq);
    cudaGetSymbolAddress((void**)&xg,   g_xg);
    cudaGetSymbolAddress((void**)&R,    g_R);
    cudaGetSymbolAddress((void**)&hst,  g_h);
    cudaGetSymbolAddress((void**)&cst,  g_c);
    cudaGetSymbolAddress((void**)&z,    g_z);
    cudaGetSymbolAddress((void**)&ahi,  g_ahi);
    cudaGetSymbolAddress((void**)&alo,  g_alo);
    cudaGetSymbolAddress((void**)&hhi,  g_hhi);
    cudaGetSymbolAddress((void**)&hlo,  g_hlo);
    cudaGetSymbolAddress((void**)&phi,  g_phi);
    cudaGetSymbolAddress((void**)&plo,  g_plo);
    cudaGetSymbolAddress((void**)&whi,  g_whi);
    cudaGetSymbolAddress((void**)&wlo,  g_wlo);

    const int M = (int)NT;
    const int upd_blocks = (int)(((size_t)Nn * HID + 255) / 256);

    // ---- split weights (once per launch; cheap) ----
    split_transpose<<<(128 * 256 + 255) / 256, 256>>>(W1, whi + OFF_W1T, wlo + OFF_W1T, FIN, H1C);
    split_transpose<<<(256 * 128 + 255) / 256, 256>>>(W2, whi + OFF_W2T, wlo + OFF_W2T, H1C, H2C);
    split_rows<<<720, 256>>>(Wih0, whi + OFF_WIH0, wlo + OFF_WIH0, G4, DSEQ, DSEQP, 0);
    split_rows<<<1024, 256>>>(Whh0, whi + OFF_WHH0, wlo + OFF_WHH0, G4, HID, HID, 0);
    split_rows<<<1024, 256>>>(Wih1, whi + OFF_WIH1, wlo + OFF_WIH1, G4, HID, HID, 0);
    split_rows<<<1024, 256>>>(Whh1, whi + OFF_WHH1, wlo + OFF_WHH1, G4, HID, HID, 0);
    split_transpose<<<(256 * 128 + 255) / 256, 256>>>(fcn_w, whi + OFF_FCNT, wlo + OFF_FCNT, HID, 128);

    // 1) support1 = nodes @ W1   [NT,128]x[128->256]
    split_rows<<<8192, 256>>>(nodes, ahi, alo, (long long)NT, FIN, FIN, 0);
    mma_gemm(ahi, alo, whi + OFF_W1T, wlo + OFF_W1T, bufA, nullptr, M, FIN, H1C, 0);

    // 2) x := b1, scatter-add spmm(support1)
    {
        init_bias_bcast<<<8192, 256>>>(bufX, b1, H1C, NT * (size_t)H1C);
        long long blocks = ((long long)Tt * Ee * 32 + 255) / 256;
        spmm_scatter<<<(unsigned)blocks, 256>>>(bufA, erow, ecol, ew, bufX, H1C, H1C, H1C, 0);
    }

    // 3) support2 = relu(x) @ W2
    split_rows<<<8192, 256>>>(bufX, ahi, alo, (long long)NT, H1C, H1C, 1);
    mma_gemm(ahi, alo, whi + OFF_W2T, wlo + OFF_W2T, bufA, nullptr, M, H1C, H2C, 0);

    // 4) seq init, spmm2
    {
        init_seq<<<8192, 256>>>(seq, b2, raw, NT * (size_t)DSEQ);
        long long blocks = ((long long)Tt * Ee * 32 + 255) / 256;
        spmm_scatter<<<(unsigned)blocks, 256>>>(bufA, erow, ecol, ew, seq, H2C, H2C, DSEQ, 1);
    }

    // 5) xg0 = seq @ Wih0^T + bih0
    split_rows<<<8192, 256>>>(seq, ahi, alo, (long long)NT, DSEQ, DSEQP, 0);
    mma_gemm(ahi, alo, whi + OFF_WIH0, wlo + OFF_WIH0, xg, bih0, M, DSEQP, G4, 0);

    // 6) LSTM layer 0 -> hseq fp32 in bufX, split hseq into ahi/alo
    for (int t = 0; t < Tt; t++) {
        if (t == 0) {
            lstm_update<<<upd_blocks, 256>>>(xg, nullptr, bhh0, cst, hst, hhi, hlo,
                                             bufX, ahi, alo, 1, 0);
        } else {
            mma_gemm(hhi, hlo, whi + OFF_WHH0, wlo + OFF_WHH0, R, bhh0, Nn, HID, G4, 0);
            lstm_update<<<upd_blocks, 256>>>(xg, R, bhh0, cst, hst, hhi, hlo,
                                             bufX, ahi, alo, 1, t);
        }
    }

    // 7) xg1 = hseq0 @ Wih1^T + bih1
    mma_gemm(ahi, alo, whi + OFF_WIH1, wlo + OFF_WIH1, xg, bih1, M, HID, G4, 0);

    // 8) LSTM layer 1 -> hseq fp32 in bufA
    for (int t = 0; t < Tt; t++) {
        if (t == 0) {
            lstm_update<<<upd_blocks, 256>>>(xg, nullptr, bhh1, cst, hst, hhi, hlo,
                                             bufA, nullptr, nullptr, 0, 0);
        } else {
            mma_gemm(hhi, hlo, whi + OFF_WHH1, wlo + OFF_WHH1, R, bhh1, Nn, HID, G4, 0);
            lstm_update<<<upd_blocks, 256>>>(xg, R, bhh1, cst, hst, hhi, hlo,
                                             bufA, nullptr, nullptr, 0, t);
        }
    }

    // 9) attention pooling -> split pooled
    attention_pool<<<Nn, HID>>>(bufA, att_w, att_b, phi, plo);

    // 10) z = relu(pooled @ fcn_w + fcn_b)
    mma_gemm(phi, plo, whi + OFF_FCNT, wlo + OFF_FCNT, z, fcn_b, Nn, HID, 128, 1);

    // 11) out = z @ out_w + out_b (fp32 fallback, Nc=64)
    {
        dim3 grid((OUTC + 63) / 64, (Nn + 63) / 64);
        sgemm_kernel<64, 64, 16, 4, 4><<<grid, 256>>>(z, out_w, out, out_b, Nn, 128, OUTC);
    }
}